// round 6
// baseline (speedup 1.0000x reference)
#include <cuda_runtime.h>
#include <cstddef>

// Problem constants (fixed by the dataset)
#define NB 2
#define NP 4096
#define NA 96
#define NF 32
#define NE 20

// Scratch for precomputed linear terms
__device__ float g_tgt[NB * NP * NF];   // scalar_reciever @ Wt + b1n
__device__ float g_src[NB * NA * NF];   // scalar @ Ws

// Constant bank: only W1e weights + biases (keeps LDC count low)
__constant__ __align__(16) float cW1e[NE * NF];
__constant__ __align__(16) float cb1e[NF];
__constant__ __align__(16) float cb2e[NF];
__constant__ __align__(16) float cb2n[NF];

// shifted softplus: log(1+e^x) - log(2), numerically stable
__device__ __forceinline__ float sspf(float x) {
    float t = __logf(1.0f + __expf(-fabsf(x)));
    return fmaxf(x, 0.0f) + t - 0.69314718055994531f;
}

// ---- packed f32x2 helpers (Blackwell FFMA2) --------------------------------
__device__ __forceinline__ void fma2(unsigned long long& acc,
                                     unsigned long long s2,
                                     unsigned long long w2) {
    asm("fma.rn.f32x2 %0, %1, %2, %0;" : "+l"(acc) : "l"(s2), "l"(w2));
}
__device__ __forceinline__ unsigned long long pack2(float s) {
    unsigned long long r;
    asm("mov.b64 %0, {%1, %1};" : "=l"(r) : "f"(s));
    return r;
}
__device__ __forceinline__ float2 unpk2(unsigned long long v) {
    float2 r;
    asm("mov.b64 {%0, %1}, %2;" : "=f"(r.x), "=f"(r.y) : "l"(v));
    return r;
}

// ---------------------------------------------------------------------------
// Precompute kernel: one warp per output row, lane = f.
// ---------------------------------------------------------------------------
__global__ void precompute_kernel(const float* __restrict__ scalar,
                                  const float* __restrict__ srecv,
                                  const float* __restrict__ W1n,
                                  const float* __restrict__ b1n)
{
    int gw   = (blockIdx.x * blockDim.x + threadIdx.x) >> 5;
    int lane = threadIdx.x & 31;

    if (gw < NB * NP) {
        float xv  = srecv[gw * NF + lane];
        float acc = b1n[lane];
        #pragma unroll
        for (int k = 0; k < NF; k++) {
            float xk = __shfl_sync(0xffffffffu, xv, k);
            acc = fmaf(xk, W1n[(NF + k) * NF + lane], acc);
        }
        g_tgt[gw * NF + lane] = acc;
    } else if (gw < NB * NP + NB * NA) {
        int r = gw - NB * NP;
        float xv  = scalar[r * NF + lane];
        float acc = 0.0f;
        #pragma unroll
        for (int k = 0; k < NF; k++) {
            float xk = __shfl_sync(0xffffffffu, xv, k);
            acc = fmaf(xk, W1n[k * NF + lane], acc);
        }
        g_src[r * NF + lane] = acc;
    }
}

// ---------------------------------------------------------------------------
// Main kernel: block = 2 (b,p)'s; thread = 2 edges (a, a+48) of one p.
// Port split: W1e on constant port, W2e/W2n on smem crossbar.
// Register diet: gates hidden layer stashed in own sbuf row (no sync),
// nodes hidden computed in two 16-wide halves. Target: 5 blocks/SM.
// ---------------------------------------------------------------------------
__global__ __launch_bounds__(96, 5) void main_kernel(
    const float* __restrict__ expansion,   // (B,P,A,E)
    const float* __restrict__ mask,        // (B,P,A,1)
    const float* __restrict__ edge,        // (B,P,A,1)
    const float* __restrict__ W2e,         // (F,F)
    const float* __restrict__ W2n,         // (F,F)
    float* __restrict__ out)               // (B,P,1,F)
{
    __shared__ __align__(16) float sW2e[NF * NF];
    __shared__ __align__(16) float sW2n[NF * NF];
    __shared__ __align__(16) float stgt[2][NF];
    // Per-thread scratch row (stride 65 -> conflict-free for both the
    // own-row scalar access pattern and the cross-row reduction).
    // Lifecycle: e1 stash -> gate stash -> combined result -> reduction.
    __shared__ float sbuf[96 * 65];

    const int t   = threadIdx.x;          // 0..95
    const int pl  = t / 48;               // which p within the block
    const int ai  = t - pl * 48;          // 0..47
    const int bp  = 2 * blockIdx.x + pl;  // global b*NP+p
    const int b   = bp >> 12;             // NP == 4096
    const int a0  = ai;                   // first edge
    const int a1  = ai + 48;              // second edge

    // ---- cooperative staging ----
    for (int i = t; i < NF * NF; i += 96) { sW2e[i] = W2e[i]; sW2n[i] = W2n[i]; }
    if (t < NF) {
        stgt[0][t] = g_tgt[(size_t)(2 * blockIdx.x) * NF + t];
        stgt[1][t] = g_tgt[(size_t)(2 * blockIdx.x + 1) * NF + t];
    }
    __syncthreads();

    float* row = &sbuf[t * 65];           // this thread's private scratch row

    // ---- per-item edge data ----
    const size_t base0 = (size_t)bp * NA + a0;
    const size_t base1 = (size_t)bp * NA + a1;

    float gm0, gm1;
    {
        float m0 = mask[base0], m1 = mask[base1];
        float d0 = edge[base0], d1 = edge[base1];
        gm0 = m0 / (1.0f + __expf(5.0f * (d0 - 3.5f)));
        gm1 = m1 / (1.0f + __expf(5.0f * (d1 - 3.5f)));
    }

    // ===== gates layer 1: ssp(x @ W1e + b1e)  [weights: constant port] =====
    unsigned long long acc0[NF / 2], acc1[NF / 2];
    {
        float x0[NE], x1[NE];
        {
            const float4* r0 = reinterpret_cast<const float4*>(expansion + base0 * NE);
            const float4* r1 = reinterpret_cast<const float4*>(expansion + base1 * NE);
            #pragma unroll
            for (int i = 0; i < NE / 4; i++) {
                float4 v0 = r0[i], v1 = r1[i];
                x0[4*i+0] = v0.x; x0[4*i+1] = v0.y; x0[4*i+2] = v0.z; x0[4*i+3] = v0.w;
                x1[4*i+0] = v1.x; x1[4*i+1] = v1.y; x1[4*i+2] = v1.z; x1[4*i+3] = v1.w;
            }
        }
        const unsigned long long* bb = reinterpret_cast<const unsigned long long*>(cb1e);
        #pragma unroll
        for (int j = 0; j < NF / 2; j++) { acc0[j] = bb[j]; acc1[j] = bb[j]; }
        #pragma unroll
        for (int e = 0; e < NE; e++) {
            unsigned long long s0 = pack2(x0[e]);
            unsigned long long s1 = pack2(x1[e]);
            const ulonglong2* w4 = reinterpret_cast<const ulonglong2*>(&cW1e[e * NF]);
            #pragma unroll
            for (int j = 0; j < NF / 4; j++) {
                ulonglong2 w = w4[j];
                fma2(acc0[2*j+0], s0, w.x); fma2(acc1[2*j+0], s1, w.x);
                fma2(acc0[2*j+1], s0, w.y); fma2(acc1[2*j+1], s1, w.y);
            }
        }
        // ssp + stash hidden layer to own row (item0 -> [0,32), item1 -> [32,64))
        #pragma unroll
        for (int j = 0; j < NF / 2; j++) {
            float2 v0 = unpk2(acc0[j]), v1 = unpk2(acc1[j]);
            row[2*j+0]      = sspf(v0.x);  row[2*j+1]      = sspf(v0.y);
            row[NF + 2*j+0] = sspf(v1.x);  row[NF + 2*j+1] = sspf(v1.y);
        }
    }   // x0/x1 dead here

    // ===== gates layer 2: @ W2e + b2e  [weights: smem, scalars: own row] ====
    {
        const unsigned long long* bb = reinterpret_cast<const unsigned long long*>(cb2e);
        #pragma unroll
        for (int j = 0; j < NF / 2; j++) { acc0[j] = bb[j]; acc1[j] = bb[j]; }
    }
    #pragma unroll
    for (int k = 0; k < NF; k++) {
        unsigned long long s0 = pack2(row[k]);
        unsigned long long s1 = pack2(row[NF + k]);
        const ulonglong2* w4 = reinterpret_cast<const ulonglong2*>(&sW2e[k * NF]);
        #pragma unroll
        for (int j = 0; j < NF / 4; j++) {
            ulonglong2 w = w4[j];
            fma2(acc0[2*j+0], s0, w.x); fma2(acc1[2*j+0], s1, w.x);
            fma2(acc0[2*j+1], s0, w.y); fma2(acc1[2*j+1], s1, w.y);
        }
    }
    // overwrite own row with gm * gate (all reads of the e1 stash are done)
    #pragma unroll
    for (int j = 0; j < NF / 2; j++) {
        float2 v0 = unpk2(acc0[j]), v1 = unpk2(acc1[j]);
        row[2*j+0]      = gm0 * v0.x;  row[2*j+1]      = gm0 * v0.y;
        row[NF + 2*j+0] = gm1 * v1.x;  row[NF + 2*j+1] = gm1 * v1.y;
    }

    // ===== nodes path: ssp(src[a] + tgt[p]) @ W2n + b2n  [two halves] =======
    {
        const unsigned long long* bb = reinterpret_cast<const unsigned long long*>(cb2n);
        #pragma unroll
        for (int j = 0; j < NF / 2; j++) { acc0[j] = bb[j]; acc1[j] = bb[j]; }
    }
    const float4* s0p = reinterpret_cast<const float4*>(g_src + ((size_t)b * NA + a0) * NF);
    const float4* s1p = reinterpret_cast<const float4*>(g_src + ((size_t)b * NA + a1) * NF);

    #pragma unroll
    for (int h = 0; h < 2; h++) {                 // half = 16 k's
        float n0[NF / 2], n1[NF / 2];
        #pragma unroll
        for (int q = 0; q < NF / 8; q++) {        // 4 float4 per half
            int qq = h * (NF / 8) + q;
            float4 v0 = s0p[qq], v1 = s1p[qq];
            float t0 = stgt[pl][4*qq+0], t1 = stgt[pl][4*qq+1];
            float t2 = stgt[pl][4*qq+2], t3 = stgt[pl][4*qq+3];
            n0[4*q+0] = sspf(v0.x + t0); n0[4*q+1] = sspf(v0.y + t1);
            n0[4*q+2] = sspf(v0.z + t2); n0[4*q+3] = sspf(v0.w + t3);
            n1[4*q+0] = sspf(v1.x + t0); n1[4*q+1] = sspf(v1.y + t1);
            n1[4*q+2] = sspf(v1.z + t2); n1[4*q+3] = sspf(v1.w + t3);
        }
        #pragma unroll
        for (int kk = 0; kk < NF / 2; kk++) {
            int k = h * (NF / 2) + kk;
            unsigned long long s0 = pack2(n0[kk]);
            unsigned long long s1 = pack2(n1[kk]);
            const ulonglong2* w4 = reinterpret_cast<const ulonglong2*>(&sW2n[k * NF]);
            #pragma unroll
            for (int j = 0; j < NF / 4; j++) {
                ulonglong2 w = w4[j];
                fma2(acc0[2*j+0], s0, w.x); fma2(acc1[2*j+0], s1, w.x);
                fma2(acc0[2*j+1], s0, w.y); fma2(acc1[2*j+1], s1, w.y);
            }
        }
    }

    // ---- combine: r_f = stash0_f*node0_f + stash1_f*node1_f (in-place) ----
    // Writes hit slots [0,32); reads of [32,64) are unaffected (own row only).
    #pragma unroll
    for (int j = 0; j < NF / 2; j++) {
        float2 v0 = unpk2(acc0[j]), v1 = unpk2(acc1[j]);
        float r0 = fmaf(row[2*j+0], v0.x, row[NF + 2*j+0] * v1.x);
        float r1 = fmaf(row[2*j+1], v0.y, row[NF + 2*j+1] * v1.y);
        row[2*j+0] = r0;
        row[2*j+1] = r1;
    }

    __syncthreads();

    // ---- reduce 48 thread-rows per p, write coalesced output ----
    if (t < NF) {
        float s = 0.0f;
        #pragma unroll
        for (int r2 = 0; r2 < 48; r2++) s += sbuf[r2 * 65 + t];
        out[(size_t)(2 * blockIdx.x) * NF + t] = s;
    } else if (t >= 48 && t < 48 + NF) {
        int f = t - 48;
        float s = 0.0f;
        #pragma unroll
        for (int r2 = 48; r2 < 96; r2++) s += sbuf[r2 * 65 + f];
        out[(size_t)(2 * blockIdx.x + 1) * NF + f] = s;
    }
}

// ---------------------------------------------------------------------------
// Launch
// ---------------------------------------------------------------------------
extern "C" void kernel_launch(void* const* d_in, const int* in_sizes, int n_in,
                              void* d_out, int out_size)
{
    const float* scalar    = (const float*)d_in[0];
    const float* srecv     = (const float*)d_in[1];
    const float* expansion = (const float*)d_in[2];
    const float* mask      = (const float*)d_in[3];
    const float* edge      = (const float*)d_in[4];
    const float* W1e       = (const float*)d_in[5];
    const float* b1e       = (const float*)d_in[6];
    const float* W2e       = (const float*)d_in[7];
    const float* b2e       = (const float*)d_in[8];
    const float* W1n       = (const float*)d_in[9];
    const float* b1n       = (const float*)d_in[10];
    const float* W2n       = (const float*)d_in[11];
    const float* b2n       = (const float*)d_in[12];
    float* out = (float*)d_out;

    // Stage W1e + biases into the constant bank (D2D async: graph-capturable)
    cudaMemcpyToSymbolAsync(cW1e, W1e, NE * NF * sizeof(float), 0,
                            cudaMemcpyDeviceToDevice, 0);
    cudaMemcpyToSymbolAsync(cb1e, b1e, NF * sizeof(float), 0,
                            cudaMemcpyDeviceToDevice, 0);
    cudaMemcpyToSymbolAsync(cb2e, b2e, NF * sizeof(float), 0,
                            cudaMemcpyDeviceToDevice, 0);
    cudaMemcpyToSymbolAsync(cb2n, b2n, NF * sizeof(float), 0,
                            cudaMemcpyDeviceToDevice, 0);

    // Precompute src/tgt linear terms: one warp per row
    int rows    = NB * NP + NB * NA;               // 8384
    int threads = 256;
    int blocks  = (rows * 32 + threads - 1) / threads;
    precompute_kernel<<<blocks, threads>>>(scalar, srecv, W1n, b1n);

    // Main fused kernel: one block per 2 (b,p)'s
    main_kernel<<<NB * NP / 2, 96>>>(expansion, mask, edge, W2e, W2n, out);
}

// round 7
// speedup vs baseline: 1.6069x; 1.6069x over previous
#include <cuda_runtime.h>
#include <cstddef>

// Problem constants (fixed by the dataset)
#define NB 2
#define NP 4096
#define NA 96
#define NF 32
#define NE 20

// Scratch for precomputed linear terms
__device__ float g_tgt[NB * NP * NF];   // scalar_reciever @ Wt + b1n
__device__ float g_src[NB * NA * NF];   // scalar @ Ws

// Gates layer-1 weights on the constant port (off both smem crossbar and L1)
__constant__ __align__(16) float cW1e[NE * NF];
__constant__ __align__(16) float cW2e[NF * NF];
__constant__ __align__(16) float cb1e[NF];
__constant__ __align__(16) float cb2e[NF];

// shifted softplus: log(1+e^x) - log(2), numerically stable
__device__ __forceinline__ float sspf(float x) {
    float t = __logf(1.0f + __expf(-fabsf(x)));
    return fmaxf(x, 0.0f) + t - 0.69314718055994531f;
}

// ---- packed f32x2 helpers (Blackwell FFMA2) --------------------------------
__device__ __forceinline__ void fma2(unsigned long long& acc,
                                     unsigned long long s2,
                                     unsigned long long w2) {
    asm("fma.rn.f32x2 %0, %1, %2, %0;" : "+l"(acc) : "l"(s2), "l"(w2));
}
__device__ __forceinline__ unsigned long long pack2(float s) {
    unsigned long long r;
    asm("mov.b64 %0, {%1, %1};" : "=l"(r) : "f"(s));
    return r;
}
__device__ __forceinline__ float2 unpk2(unsigned long long v) {
    float2 r;
    asm("mov.b64 {%0, %1}, %2;" : "=f"(r.x), "=f"(r.y) : "l"(v));
    return r;
}

// ---------------------------------------------------------------------------
// Precompute kernel: one warp per output row, lane = f.
// ---------------------------------------------------------------------------
__global__ void precompute_kernel(const float* __restrict__ scalar,
                                  const float* __restrict__ srecv,
                                  const float* __restrict__ W1n,
                                  const float* __restrict__ b1n)
{
    int gw   = (blockIdx.x * blockDim.x + threadIdx.x) >> 5;
    int lane = threadIdx.x & 31;

    if (gw < NB * NP) {
        float xv  = srecv[gw * NF + lane];
        float acc = b1n[lane];
        #pragma unroll
        for (int k = 0; k < NF; k++) {
            float xk = __shfl_sync(0xffffffffu, xv, k);
            acc = fmaf(xk, W1n[(NF + k) * NF + lane], acc);
        }
        g_tgt[gw * NF + lane] = acc;
    } else if (gw < NB * NP + NB * NA) {
        int r = gw - NB * NP;
        float xv  = scalar[r * NF + lane];
        float acc = 0.0f;
        #pragma unroll
        for (int k = 0; k < NF; k++) {
            float xk = __shfl_sync(0xffffffffu, xv, k);
            acc = fmaf(xk, W1n[k * NF + lane], acc);
        }
        g_src[r * NF + lane] = acc;
    }
}

// ---------------------------------------------------------------------------
// Main kernel: block = 2 (b,p)'s; thread = 2 edges (a, a+48) of one p.
// Identical structure to the 127.5us R5 kernel; only the register cap
// changed (5 blocks/SM target -> <=136 regs) for +25% warps/SMSP.
// Gates weights via constant port; nodes weights via smem crossbar.
// All GEMM scalars stay in registers (R6 lesson).
// ---------------------------------------------------------------------------
__global__ __launch_bounds__(96, 5) void main_kernel(
    const float* __restrict__ expansion,   // (B,P,A,E)
    const float* __restrict__ mask,        // (B,P,A,1)
    const float* __restrict__ edge,        // (B,P,A,1)
    const float* __restrict__ W2n,         // (F,F)
    const float* __restrict__ b2n,         // (F)
    float* __restrict__ out)               // (B,P,1,F)
{
    __shared__ __align__(16) float sW2n[NF * NF];
    __shared__ __align__(16) float sb2n[NF];
    __shared__ __align__(16) float stgt[2][NF];
    // Reused: gate stash (64 f/thread, stride 65) then reduction buffer.
    __shared__ float sbuf[96 * 65];

    const int t   = threadIdx.x;          // 0..95
    const int pl  = t / 48;               // which p within the block
    const int ai  = t - pl * 48;          // 0..47
    const int bp  = 2 * blockIdx.x + pl;  // global b*NP+p
    const int b   = bp >> 12;             // NP == 4096
    const int a0  = ai;                   // first edge
    const int a1  = ai + 48;              // second edge

    // ---- cooperative staging ----
    for (int i = t; i < NF * NF; i += 96) sW2n[i] = W2n[i];
    if (t < NF) {
        sb2n[t] = b2n[t];
        stgt[0][t] = g_tgt[(size_t)(2 * blockIdx.x) * NF + t];
        stgt[1][t] = g_tgt[(size_t)(2 * blockIdx.x + 1) * NF + t];
    }
    __syncthreads();

    // ---- per-item edge data ----
    const size_t base0 = (size_t)bp * NA + a0;
    const size_t base1 = (size_t)bp * NA + a1;

    float x0[NE], x1[NE];
    {
        const float4* r0 = reinterpret_cast<const float4*>(expansion + base0 * NE);
        const float4* r1 = reinterpret_cast<const float4*>(expansion + base1 * NE);
        #pragma unroll
        for (int i = 0; i < NE / 4; i++) {
            float4 v0 = r0[i], v1 = r1[i];
            x0[4*i+0] = v0.x; x0[4*i+1] = v0.y; x0[4*i+2] = v0.z; x0[4*i+3] = v0.w;
            x1[4*i+0] = v1.x; x1[4*i+1] = v1.y; x1[4*i+2] = v1.z; x1[4*i+3] = v1.w;
        }
    }
    float gm0, gm1;
    {
        float m0 = mask[base0], m1 = mask[base1];
        float d0 = edge[base0], d1 = edge[base1];
        gm0 = m0 / (1.0f + __expf(5.0f * (d0 - 3.5f)));
        gm1 = m1 / (1.0f + __expf(5.0f * (d1 - 3.5f)));
    }

    // ===== gates layer 1: ssp(x @ W1e + b1e)  [weights: constant port] =====
    unsigned long long acc0[NF / 2], acc1[NF / 2];
    {
        const unsigned long long* bb = reinterpret_cast<const unsigned long long*>(cb1e);
        #pragma unroll
        for (int j = 0; j < NF / 2; j++) { acc0[j] = bb[j]; acc1[j] = bb[j]; }
    }
    #pragma unroll
    for (int e = 0; e < NE; e++) {
        unsigned long long s0 = pack2(x0[e]);
        unsigned long long s1 = pack2(x1[e]);
        const ulonglong2* w4 = reinterpret_cast<const ulonglong2*>(&cW1e[e * NF]);
        #pragma unroll
        for (int j = 0; j < NF / 4; j++) {
            ulonglong2 w = w4[j];
            fma2(acc0[2*j+0], s0, w.x); fma2(acc1[2*j+0], s1, w.x);
            fma2(acc0[2*j+1], s0, w.y); fma2(acc1[2*j+1], s1, w.y);
        }
    }
    float e1g0[NF], e1g1[NF];
    #pragma unroll
    for (int j = 0; j < NF / 2; j++) {
        float2 v0 = unpk2(acc0[j]), v1 = unpk2(acc1[j]);
        e1g0[2*j+0] = sspf(v0.x); e1g0[2*j+1] = sspf(v0.y);
        e1g1[2*j+0] = sspf(v1.x); e1g1[2*j+1] = sspf(v1.y);
    }

    // ===== gates layer 2: @ W2e + b2e  [weights: constant port] =====
    {
        const unsigned long long* bb = reinterpret_cast<const unsigned long long*>(cb2e);
        #pragma unroll
        for (int j = 0; j < NF / 2; j++) { acc0[j] = bb[j]; acc1[j] = bb[j]; }
    }
    #pragma unroll
    for (int k = 0; k < NF; k++) {
        unsigned long long s0 = pack2(e1g0[k]);
        unsigned long long s1 = pack2(e1g1[k]);
        const ulonglong2* w4 = reinterpret_cast<const ulonglong2*>(&cW2e[k * NF]);
        #pragma unroll
        for (int j = 0; j < NF / 4; j++) {
            ulonglong2 w = w4[j];
            fma2(acc0[2*j+0], s0, w.x); fma2(acc1[2*j+0], s1, w.x);
            fma2(acc0[2*j+1], s0, w.y); fma2(acc1[2*j+1], s1, w.y);
        }
    }
    // stash gm * gate to smem (frees 64 registers for the nodes GEMM)
    {
        float* st = &sbuf[t * 65];
        #pragma unroll
        for (int j = 0; j < NF / 2; j++) {
            float2 v0 = unpk2(acc0[j]), v1 = unpk2(acc1[j]);
            st[2*j+0]      = gm0 * v0.x;  st[2*j+1]      = gm0 * v0.y;
            st[NF + 2*j+0] = gm1 * v1.x;  st[NF + 2*j+1] = gm1 * v1.y;
        }
    }

    // ===== nodes path: ssp(src[a] + tgt[p]) @ W2n + b2n  [weights: smem] ====
    float n1g0[NF], n1g1[NF];
    {
        const float4* s0 = reinterpret_cast<const float4*>(g_src + ((size_t)b * NA + a0) * NF);
        const float4* s1 = reinterpret_cast<const float4*>(g_src + ((size_t)b * NA + a1) * NF);
        #pragma unroll
        for (int q = 0; q < NF / 4; q++) {
            float4 v0 = s0[q], v1 = s1[q];
            float t0 = stgt[pl][4*q+0], t1 = stgt[pl][4*q+1];
            float t2 = stgt[pl][4*q+2], t3 = stgt[pl][4*q+3];
            n1g0[4*q+0] = sspf(v0.x + t0); n1g0[4*q+1] = sspf(v0.y + t1);
            n1g0[4*q+2] = sspf(v0.z + t2); n1g0[4*q+3] = sspf(v0.w + t3);
            n1g1[4*q+0] = sspf(v1.x + t0); n1g1[4*q+1] = sspf(v1.y + t1);
            n1g1[4*q+2] = sspf(v1.z + t2); n1g1[4*q+3] = sspf(v1.w + t3);
        }
    }
    {
        const unsigned long long* bb = reinterpret_cast<const unsigned long long*>(sb2n);
        #pragma unroll
        for (int j = 0; j < NF / 2; j++) { acc0[j] = bb[j]; acc1[j] = bb[j]; }
    }
    #pragma unroll
    for (int k = 0; k < NF; k++) {
        unsigned long long s0 = pack2(n1g0[k]);
        unsigned long long s1 = pack2(n1g1[k]);
        const ulonglong2* w4 = reinterpret_cast<const ulonglong2*>(&sW2n[k * NF]);
        #pragma unroll
        for (int j = 0; j < NF / 4; j++) {
            ulonglong2 w = w4[j];
            fma2(acc0[2*j+0], s0, w.x); fma2(acc1[2*j+0], s1, w.x);
            fma2(acc0[2*j+1], s0, w.y); fma2(acc1[2*j+1], s1, w.y);
        }
    }

    // ---- combine both items in registers: r_f = st0_f*n0_f + st1_f*n1_f ----
    float r[NF];
    {
        const float* st = &sbuf[t * 65];
        #pragma unroll
        for (int j = 0; j < NF / 2; j++) {
            float2 v0 = unpk2(acc0[j]), v1 = unpk2(acc1[j]);
            r[2*j+0] = fmaf(st[2*j+0], v0.x, st[NF + 2*j+0] * v1.x);
            r[2*j+1] = fmaf(st[2*j+1], v0.y, st[NF + 2*j+1] * v1.y);
        }
    }

    __syncthreads();   // stash fully consumed; reuse sbuf for reduction

    #pragma unroll
    for (int f = 0; f < NF; f++) sbuf[t * 65 + f] = r[f];

    __syncthreads();

    // ---- reduce 48 thread-rows per p, write coalesced output ----
    if (t < NF) {
        float s = 0.0f;
        #pragma unroll
        for (int row = 0; row < 48; row++) s += sbuf[row * 65 + t];
        out[(size_t)(2 * blockIdx.x) * NF + t] = s;
    } else if (t >= 48 && t < 48 + NF) {
        int f = t - 48;
        float s = 0.0f;
        #pragma unroll
        for (int row = 48; row < 96; row++) s += sbuf[row * 65 + f];
        out[(size_t)(2 * blockIdx.x + 1) * NF + f] = s;
    }
}

// ---------------------------------------------------------------------------
// Launch
// ---------------------------------------------------------------------------
extern "C" void kernel_launch(void* const* d_in, const int* in_sizes, int n_in,
                              void* d_out, int out_size)
{
    const float* scalar    = (const float*)d_in[0];
    const float* srecv     = (const float*)d_in[1];
    const float* expansion = (const float*)d_in[2];
    const float* mask      = (const float*)d_in[3];
    const float* edge      = (const float*)d_in[4];
    const float* W1e       = (const float*)d_in[5];
    const float* b1e       = (const float*)d_in[6];
    const float* W2e       = (const float*)d_in[7];
    const float* b2e       = (const float*)d_in[8];
    const float* W1n       = (const float*)d_in[9];
    const float* b1n       = (const float*)d_in[10];
    const float* W2n       = (const float*)d_in[11];
    const float* b2n       = (const float*)d_in[12];
    float* out = (float*)d_out;

    // Stage gates weights into the constant bank (D2D async: graph-capturable)
    cudaMemcpyToSymbolAsync(cW1e, W1e, NE * NF * sizeof(float), 0,
                            cudaMemcpyDeviceToDevice, 0);
    cudaMemcpyToSymbolAsync(cW2e, W2e, NF * NF * sizeof(float), 0,
                            cudaMemcpyDeviceToDevice, 0);
    cudaMemcpyToSymbolAsync(cb1e, b1e, NF * sizeof(float), 0,
                            cudaMemcpyDeviceToDevice, 0);
    cudaMemcpyToSymbolAsync(cb2e, b2e, NF * sizeof(float), 0,
                            cudaMemcpyDeviceToDevice, 0);

    // Precompute src/tgt linear terms: one warp per row
    int rows    = NB * NP + NB * NA;               // 8384
    int threads = 256;
    int blocks  = (rows * 32 + threads - 1) / threads;
    precompute_kernel<<<blocks, threads>>>(scalar, srecv, W1n, b1n);

    // Main fused kernel: one block per 2 (b,p)'s
    main_kernel<<<NB * NP / 2, 96>>>(expansion, mask, edge, W2n, b2n, out);
}

// round 8
// speedup vs baseline: 1.6271x; 1.0126x over previous
#include <cuda_runtime.h>
#include <cstddef>

// Problem constants (fixed by the dataset)
#define NB 2
#define NP 4096
#define NA 96
#define NF 32
#define NE 20

// Scratch for precomputed linear terms
__device__ float g_tgt[NB * NP * NF];   // scalar_reciever @ Wt + b1n
__device__ float g_src[NB * NA * NF];   // scalar @ Ws

// Constant bank: W1e + biases only (LDC stream sized to 48% of FMA floor)
__constant__ __align__(16) float cW1e[NE * NF];
__constant__ __align__(16) float cb1e[NF];
__constant__ __align__(16) float cb2e[NF];
__constant__ __align__(16) float cb2n[NF];

// shifted softplus: log(1+e^x) - log(2), numerically stable
__device__ __forceinline__ float sspf(float x) {
    float t = __logf(1.0f + __expf(-fabsf(x)));
    return fmaxf(x, 0.0f) + t - 0.69314718055994531f;
}

// ---- packed f32x2 helpers (Blackwell FFMA2) --------------------------------
__device__ __forceinline__ void fma2(unsigned long long& acc,
                                     unsigned long long s2,
                                     unsigned long long w2) {
    asm("fma.rn.f32x2 %0, %1, %2, %0;" : "+l"(acc) : "l"(s2), "l"(w2));
}
__device__ __forceinline__ unsigned long long pack2(float s) {
    unsigned long long r;
    asm("mov.b64 %0, {%1, %1};" : "=l"(r) : "f"(s));
    return r;
}
__device__ __forceinline__ float2 unpk2(unsigned long long v) {
    float2 r;
    asm("mov.b64 {%0, %1}, %2;" : "=f"(r.x), "=f"(r.y) : "l"(v));
    return r;
}

// ---------------------------------------------------------------------------
// Precompute kernel: one warp per output row, lane = f.
// ---------------------------------------------------------------------------
__global__ void precompute_kernel(const float* __restrict__ scalar,
                                  const float* __restrict__ srecv,
                                  const float* __restrict__ W1n,
                                  const float* __restrict__ b1n)
{
    int gw   = (blockIdx.x * blockDim.x + threadIdx.x) >> 5;
    int lane = threadIdx.x & 31;

    if (gw < NB * NP) {
        float xv  = srecv[gw * NF + lane];
        float acc = b1n[lane];
        #pragma unroll
        for (int k = 0; k < NF; k++) {
            float xk = __shfl_sync(0xffffffffu, xv, k);
            acc = fmaf(xk, W1n[(NF + k) * NF + lane], acc);
        }
        g_tgt[gw * NF + lane] = acc;
    } else if (gw < NB * NP + NB * NA) {
        int r = gw - NB * NP;
        float xv  = scalar[r * NF + lane];
        float acc = 0.0f;
        #pragma unroll
        for (int k = 0; k < NF; k++) {
            float xk = __shfl_sync(0xffffffffu, xv, k);
            acc = fmaf(xk, W1n[k * NF + lane], acc);
        }
        g_src[r * NF + lane] = acc;
    }
}

// ---------------------------------------------------------------------------
// Main kernel: block = one (b,p), thread = one a (ITEMS=1).
// Port split: W1e via constant port (1280 cyc/warp), W2e+W2n via smem
// crossbar (2048 cyc/warp) — both below the 2688-cyc FMA2 floor.
// ITEMS=1 register budget (~100) -> 6 blocks/SM -> 4.5 warps/SMSP.
// ---------------------------------------------------------------------------
__global__ __launch_bounds__(96, 6) void main_kernel(
    const float* __restrict__ expansion,   // (B,P,A,E)
    const float* __restrict__ mask,        // (B,P,A,1)
    const float* __restrict__ edge,        // (B,P,A,1)
    const float* __restrict__ W2e,         // (F,F)
    const float* __restrict__ W2n,         // (F,F)
    float* __restrict__ out)               // (B,P,1,F)
{
    __shared__ __align__(16) float sW2e[NF * NF];
    __shared__ __align__(16) float sW2n[NF * NF];
    __shared__ __align__(16) float stgt[NF];
    __shared__ float sred[NA * 33];   // padded stride 33: conflict-free

    const int bp = blockIdx.x;       // b*NP + p
    const int a  = threadIdx.x;      // 0..95
    const int b  = bp >> 12;         // NP == 4096

    // ---- cooperative staging ----
    for (int i = a; i < NF * NF; i += 96) { sW2e[i] = W2e[i]; sW2n[i] = W2n[i]; }
    if (a < NF) stgt[a] = g_tgt[(size_t)bp * NF + a];
    __syncthreads();

    // --- per-thread edge data ---
    float x[NE];
    {
        const float4* xr = reinterpret_cast<const float4*>(
            expansion + ((size_t)bp * NA + a) * NE);   // 80B rows: 16B-aligned
        #pragma unroll
        for (int i = 0; i < NE / 4; i++) {
            float4 v = xr[i];
            x[4 * i + 0] = v.x; x[4 * i + 1] = v.y;
            x[4 * i + 2] = v.z; x[4 * i + 3] = v.w;
        }
    }
    float m = mask[(size_t)bp * NA + a];
    float d = edge[(size_t)bp * NA + a];
    // mask * (1 - sigmoid(5*(d-3.5))) = mask / (1 + exp(5*(d-3.5)))
    float gm = m / (1.0f + __expf(5.0f * (d - 3.5f)));

    // ===== gates layer 1: ssp(x @ W1e + b1e)  [weights: constant port] =====
    unsigned long long acc[NF / 2];
    {
        const unsigned long long* bb =
            reinterpret_cast<const unsigned long long*>(cb1e);
        #pragma unroll
        for (int j = 0; j < NF / 2; j++) acc[j] = bb[j];
    }
    #pragma unroll
    for (int e = 0; e < NE; e++) {
        unsigned long long s2 = pack2(x[e]);
        const ulonglong2* w4 = reinterpret_cast<const ulonglong2*>(&cW1e[e * NF]);
        #pragma unroll
        for (int j = 0; j < NF / 4; j++) {
            ulonglong2 w = w4[j];
            fma2(acc[2 * j + 0], s2, w.x);
            fma2(acc[2 * j + 1], s2, w.y);
        }
    }
    float e1[NF];
    #pragma unroll
    for (int j = 0; j < NF / 2; j++) {
        float2 v = unpk2(acc[j]);
        e1[2 * j + 0] = sspf(v.x);
        e1[2 * j + 1] = sspf(v.y);
    }

    // ===== gates layer 2: @ W2e + b2e  [weights: smem crossbar] =====
    unsigned long long gate2[NF / 2];
    {
        const unsigned long long* bb =
            reinterpret_cast<const unsigned long long*>(cb2e);
        #pragma unroll
        for (int j = 0; j < NF / 2; j++) gate2[j] = bb[j];
    }
    #pragma unroll
    for (int k = 0; k < NF; k++) {
        unsigned long long s2 = pack2(e1[k]);
        const ulonglong2* w4 = reinterpret_cast<const ulonglong2*>(&sW2e[k * NF]);
        #pragma unroll
        for (int j = 0; j < NF / 4; j++) {
            ulonglong2 w = w4[j];
            fma2(gate2[2 * j + 0], s2, w.x);
            fma2(gate2[2 * j + 1], s2, w.y);
        }
    }

    // ===== nodes path: ssp(src[a] + tgt[p]) @ W2n + b2n  [weights: smem] ====
    {
        const float4* srow = reinterpret_cast<const float4*>(
            g_src + ((size_t)b * NA + a) * NF);
        #pragma unroll
        for (int q = 0; q < NF / 4; q++) {
            float4 v = srow[q];
            e1[4 * q + 0] = sspf(v.x + stgt[4 * q + 0]);
            e1[4 * q + 1] = sspf(v.y + stgt[4 * q + 1]);
            e1[4 * q + 2] = sspf(v.z + stgt[4 * q + 2]);
            e1[4 * q + 3] = sspf(v.w + stgt[4 * q + 3]);
        }
    }
    {
        const unsigned long long* bb =
            reinterpret_cast<const unsigned long long*>(cb2n);
        #pragma unroll
        for (int j = 0; j < NF / 2; j++) acc[j] = bb[j];
    }
    #pragma unroll
    for (int k = 0; k < NF; k++) {
        unsigned long long s2 = pack2(e1[k]);
        const ulonglong2* w4 = reinterpret_cast<const ulonglong2*>(&sW2n[k * NF]);
        #pragma unroll
        for (int j = 0; j < NF / 4; j++) {
            ulonglong2 w = w4[j];
            fma2(acc[2 * j + 0], s2, w.x);
            fma2(acc[2 * j + 1], s2, w.y);
        }
    }

    // --- contribution: mask*cut * gate ⊙ node ---
    #pragma unroll
    for (int j = 0; j < NF / 2; j++) {
        float2 g = unpk2(gate2[j]);
        float2 n = unpk2(acc[j]);
        sred[a * 33 + 2 * j + 0] = gm * g.x * n.x;
        sred[a * 33 + 2 * j + 1] = gm * g.y * n.y;
    }

    __syncthreads();

    // reduce over a (warp 0), write coalesced output
    if (a < NF) {
        float s = 0.0f;
        #pragma unroll
        for (int aa = 0; aa < NA; aa++) s += sred[aa * 33 + a];
        out[(size_t)bp * NF + a] = s;
    }
}

// ---------------------------------------------------------------------------
// Launch
// ---------------------------------------------------------------------------
extern "C" void kernel_launch(void* const* d_in, const int* in_sizes, int n_in,
                              void* d_out, int out_size)
{
    const float* scalar    = (const float*)d_in[0];
    const float* srecv     = (const float*)d_in[1];
    const float* expansion = (const float*)d_in[2];
    const float* mask      = (const float*)d_in[3];
    const float* edge      = (const float*)d_in[4];
    const float* W1e       = (const float*)d_in[5];
    const float* b1e       = (const float*)d_in[6];
    const float* W2e       = (const float*)d_in[7];
    const float* b2e       = (const float*)d_in[8];
    const float* W1n       = (const float*)d_in[9];
    const float* b1n       = (const float*)d_in[10];
    const float* W2n       = (const float*)d_in[11];
    const float* b2n       = (const float*)d_in[12];
    float* out = (float*)d_out;

    // Stage W1e + biases into the constant bank (D2D async: graph-capturable)
    cudaMemcpyToSymbolAsync(cW1e, W1e, NE * NF * sizeof(float), 0,
                            cudaMemcpyDeviceToDevice, 0);
    cudaMemcpyToSymbolAsync(cb1e, b1e, NF * sizeof(float), 0,
                            cudaMemcpyDeviceToDevice, 0);
    cudaMemcpyToSymbolAsync(cb2e, b2e, NF * sizeof(float), 0,
                            cudaMemcpyDeviceToDevice, 0);
    cudaMemcpyToSymbolAsync(cb2n, b2n, NF * sizeof(float), 0,
                            cudaMemcpyDeviceToDevice, 0);

    // Precompute src/tgt linear terms: one warp per row
    int rows    = NB * NP + NB * NA;               // 8384
    int threads = 256;
    int blocks  = (rows * 32 + threads - 1) / threads;
    precompute_kernel<<<blocks, threads>>>(scalar, srecv, W1n, b1n);

    // Main fused kernel: one block per (b,p)
    main_kernel<<<NB * NP, 96>>>(expansion, mask, edge, W2e, W2n, out);
}

// round 9
// speedup vs baseline: 1.7017x; 1.0459x over previous
#include <cuda_runtime.h>
#include <cstddef>

// Problem constants (fixed by the dataset)
#define NB 2
#define NP 4096
#define NA 96
#define NF 32
#define NE 20

// Scratch for precomputed linear terms
__device__ float g_tgt[NB * NP * NF];   // scalar_reciever @ Wt + b1n
__device__ float g_src[NB * NA * NF];   // scalar @ Ws

// Constant bank: W1e + biases only (LDC stream ~24% of FMA floor)
__constant__ __align__(16) float cW1e[NE * NF];
__constant__ __align__(16) float cb1e[NF];
__constant__ __align__(16) float cb2e[NF];
__constant__ __align__(16) float cb2n[NF];

// shifted softplus: log(1+e^x) - log(2), numerically stable
__device__ __forceinline__ float sspf(float x) {
    float t = __logf(1.0f + __expf(-fabsf(x)));
    return fmaxf(x, 0.0f) + t - 0.69314718055994531f;
}

// ---- packed f32x2 helpers (Blackwell FFMA2) --------------------------------
__device__ __forceinline__ void fma2(unsigned long long& acc,
                                     unsigned long long s2,
                                     unsigned long long w2) {
    asm("fma.rn.f32x2 %0, %1, %2, %0;" : "+l"(acc) : "l"(s2), "l"(w2));
}
__device__ __forceinline__ unsigned long long pack2(float s) {
    unsigned long long r;
    asm("mov.b64 %0, {%1, %1};" : "=l"(r) : "f"(s));
    return r;
}
__device__ __forceinline__ float2 unpk2(unsigned long long v) {
    float2 r;
    asm("mov.b64 {%0, %1}, %2;" : "=f"(r.x), "=f"(r.y) : "l"(v));
    return r;
}

// ---------------------------------------------------------------------------
// Precompute kernel: one warp per output row, lane = f.
// ---------------------------------------------------------------------------
__global__ void precompute_kernel(const float* __restrict__ scalar,
                                  const float* __restrict__ srecv,
                                  const float* __restrict__ W1n,
                                  const float* __restrict__ b1n)
{
    int gw   = (blockIdx.x * blockDim.x + threadIdx.x) >> 5;
    int lane = threadIdx.x & 31;

    if (gw < NB * NP) {
        float xv  = srecv[gw * NF + lane];
        float acc = b1n[lane];
        #pragma unroll
        for (int k = 0; k < NF; k++) {
            float xk = __shfl_sync(0xffffffffu, xv, k);
            acc = fmaf(xk, W1n[(NF + k) * NF + lane], acc);
        }
        g_tgt[gw * NF + lane] = acc;
    } else if (gw < NB * NP + NB * NA) {
        int r = gw - NB * NP;
        float xv  = scalar[r * NF + lane];
        float acc = 0.0f;
        #pragma unroll
        for (int k = 0; k < NF; k++) {
            float xk = __shfl_sync(0xffffffffu, xv, k);
            acc = fmaf(xk, W1n[k * NF + lane], acc);
        }
        g_src[r * NF + lane] = acc;
    }
}

// ---------------------------------------------------------------------------
// Main kernel: block = 2 (b,p)'s; thread = 2 edges (a, a+48) of one p.
// R5 structure + (a) W2e moved to smem (const keeps only W1e),
// (b) just-in-time ssp inside the GEMM loops (lookahead 4) so MUFU issue
// is interleaved with FMA instead of bursting 128-deep between GEMMs.
// ---------------------------------------------------------------------------
__global__ __launch_bounds__(96, 4) void main_kernel(
    const float* __restrict__ expansion,   // (B,P,A,E)
    const float* __restrict__ mask,        // (B,P,A,1)
    const float* __restrict__ edge,        // (B,P,A,1)
    const float* __restrict__ W2e,         // (F,F)
    const float* __restrict__ W2n,         // (F,F)
    float* __restrict__ out)               // (B,P,1,F)
{
    __shared__ __align__(16) float sW2e[NF * NF];
    __shared__ __align__(16) float sW2n[NF * NF];
    __shared__ __align__(16) float stgt[2][NF];
    // Reused: gate stash (64 f/thread, stride 65) then reduction buffer.
    __shared__ float sbuf[96 * 65];

    const int t   = threadIdx.x;          // 0..95
    const int pl  = t / 48;               // which p within the block
    const int ai  = t - pl * 48;          // 0..47
    const int bp  = 2 * blockIdx.x + pl;  // global b*NP+p
    const int b   = bp >> 12;             // NP == 4096
    const int a0  = ai;                   // first edge
    const int a1  = ai + 48;              // second edge

    // ---- cooperative staging ----
    for (int i = t; i < NF * NF; i += 96) { sW2e[i] = W2e[i]; sW2n[i] = W2n[i]; }
    if (t < NF) {
        stgt[0][t] = g_tgt[(size_t)(2 * blockIdx.x) * NF + t];
        stgt[1][t] = g_tgt[(size_t)(2 * blockIdx.x + 1) * NF + t];
    }
    __syncthreads();

    // ---- per-item edge data ----
    const size_t base0 = (size_t)bp * NA + a0;
    const size_t base1 = (size_t)bp * NA + a1;

    float x0[NE], x1[NE];
    {
        const float4* r0 = reinterpret_cast<const float4*>(expansion + base0 * NE);
        const float4* r1 = reinterpret_cast<const float4*>(expansion + base1 * NE);
        #pragma unroll
        for (int i = 0; i < NE / 4; i++) {
            float4 v0 = r0[i], v1 = r1[i];
            x0[4*i+0] = v0.x; x0[4*i+1] = v0.y; x0[4*i+2] = v0.z; x0[4*i+3] = v0.w;
            x1[4*i+0] = v1.x; x1[4*i+1] = v1.y; x1[4*i+2] = v1.z; x1[4*i+3] = v1.w;
        }
    }
    float gm0, gm1;
    {
        float m0 = mask[base0], m1 = mask[base1];
        float d0 = edge[base0], d1 = edge[base1];
        gm0 = m0 / (1.0f + __expf(5.0f * (d0 - 3.5f)));
        gm1 = m1 / (1.0f + __expf(5.0f * (d1 - 3.5f)));
    }

    // ===== gates layer 1: x @ W1e + b1e  [weights: constant port] =====
    unsigned long long acc0[NF / 2], acc1[NF / 2];
    {
        const unsigned long long* bb = reinterpret_cast<const unsigned long long*>(cb1e);
        #pragma unroll
        for (int j = 0; j < NF / 2; j++) { acc0[j] = bb[j]; acc1[j] = bb[j]; }
    }
    #pragma unroll
    for (int e = 0; e < NE; e++) {
        unsigned long long s0 = pack2(x0[e]);
        unsigned long long s1 = pack2(x1[e]);
        const ulonglong2* w4 = reinterpret_cast<const ulonglong2*>(&cW1e[e * NF]);
        #pragma unroll
        for (int j = 0; j < NF / 4; j++) {
            ulonglong2 w = w4[j];
            fma2(acc0[2*j+0], s0, w.x); fma2(acc1[2*j+0], s1, w.x);
            fma2(acc0[2*j+1], s0, w.y); fma2(acc1[2*j+1], s1, w.y);
        }
    }
    // unpack raw pre-activations (ALU only — no MUFU burst here)
    float e1g0[NF], e1g1[NF];
    #pragma unroll
    for (int j = 0; j < NF / 2; j++) {
        float2 v0 = unpk2(acc0[j]), v1 = unpk2(acc1[j]);
        e1g0[2*j+0] = v0.x; e1g0[2*j+1] = v0.y;
        e1g1[2*j+0] = v1.x; e1g1[2*j+1] = v1.y;
    }
    // prologue: ssp for the first 4 k's
    #pragma unroll
    for (int k = 0; k < 4; k++) { e1g0[k] = sspf(e1g0[k]); e1g1[k] = sspf(e1g1[k]); }

    // ===== gates layer 2: @ W2e + b2e  [weights: smem; ssp JIT] =====
    {
        const unsigned long long* bb = reinterpret_cast<const unsigned long long*>(cb2e);
        #pragma unroll
        for (int j = 0; j < NF / 2; j++) { acc0[j] = bb[j]; acc1[j] = bb[j]; }
    }
    #pragma unroll
    for (int k = 0; k < NF; k++) {
        if (k + 4 < NF) {   // JIT ssp, lookahead 4 (static guard, fully unrolled)
            e1g0[k + 4] = sspf(e1g0[k + 4]);
            e1g1[k + 4] = sspf(e1g1[k + 4]);
        }
        unsigned long long s0 = pack2(e1g0[k]);
        unsigned long long s1 = pack2(e1g1[k]);
        const ulonglong2* w4 = reinterpret_cast<const ulonglong2*>(&sW2e[k * NF]);
        #pragma unroll
        for (int j = 0; j < NF / 4; j++) {
            ulonglong2 w = w4[j];
            fma2(acc0[2*j+0], s0, w.x); fma2(acc1[2*j+0], s1, w.x);
            fma2(acc0[2*j+1], s0, w.y); fma2(acc1[2*j+1], s1, w.y);
        }
    }
    // stash gm * gate to smem (frees 64 registers for the nodes GEMM)
    {
        float* st = &sbuf[t * 65];
        #pragma unroll
        for (int j = 0; j < NF / 2; j++) {
            float2 v0 = unpk2(acc0[j]), v1 = unpk2(acc1[j]);
            st[2*j+0]      = gm0 * v0.x;  st[2*j+1]      = gm0 * v0.y;
            st[NF + 2*j+0] = gm1 * v1.x;  st[NF + 2*j+1] = gm1 * v1.y;
        }
    }

    // ===== nodes path: ssp(src[a] + tgt[p]) @ W2n + b2n  [ssp JIT] =====
    float n1g0[NF], n1g1[NF];
    {
        // raw pre-activations: ALU adds only
        const float4* s0 = reinterpret_cast<const float4*>(g_src + ((size_t)b * NA + a0) * NF);
        const float4* s1 = reinterpret_cast<const float4*>(g_src + ((size_t)b * NA + a1) * NF);
        #pragma unroll
        for (int q = 0; q < NF / 4; q++) {
            float4 v0 = s0[q], v1 = s1[q];
            float t0 = stgt[pl][4*q+0], t1 = stgt[pl][4*q+1];
            float t2 = stgt[pl][4*q+2], t3 = stgt[pl][4*q+3];
            n1g0[4*q+0] = v0.x + t0; n1g0[4*q+1] = v0.y + t1;
            n1g0[4*q+2] = v0.z + t2; n1g0[4*q+3] = v0.w + t3;
            n1g1[4*q+0] = v1.x + t0; n1g1[4*q+1] = v1.y + t1;
            n1g1[4*q+2] = v1.z + t2; n1g1[4*q+3] = v1.w + t3;
        }
    }
    #pragma unroll
    for (int k = 0; k < 4; k++) { n1g0[k] = sspf(n1g0[k]); n1g1[k] = sspf(n1g1[k]); }

    {
        const unsigned long long* bb = reinterpret_cast<const unsigned long long*>(cb2n);
        #pragma unroll
        for (int j = 0; j < NF / 2; j++) { acc0[j] = bb[j]; acc1[j] = bb[j]; }
    }
    #pragma unroll
    for (int k = 0; k < NF; k++) {
        if (k + 4 < NF) {   // JIT ssp, lookahead 4
            n1g0[k + 4] = sspf(n1g0[k + 4]);
            n1g1[k + 4] = sspf(n1g1[k + 4]);
        }
        unsigned long long s0 = pack2(n1g0[k]);
        unsigned long long s1 = pack2(n1g1[k]);
        const ulonglong2* w4 = reinterpret_cast<const ulonglong2*>(&sW2n[k * NF]);
        #pragma unroll
        for (int j = 0; j < NF / 4; j++) {
            ulonglong2 w = w4[j];
            fma2(acc0[2*j+0], s0, w.x); fma2(acc1[2*j+0], s1, w.x);
            fma2(acc0[2*j+1], s0, w.y); fma2(acc1[2*j+1], s1, w.y);
        }
    }

    // ---- combine both items in registers: r_f = st0_f*n0_f + st1_f*n1_f ----
    float r[NF];
    {
        const float* st = &sbuf[t * 65];
        #pragma unroll
        for (int j = 0; j < NF / 2; j++) {
            float2 v0 = unpk2(acc0[j]), v1 = unpk2(acc1[j]);
            r[2*j+0] = fmaf(st[2*j+0], v0.x, st[NF + 2*j+0] * v1.x);
            r[2*j+1] = fmaf(st[2*j+1], v0.y, st[NF + 2*j+1] * v1.y);
        }
    }

    __syncthreads();   // stash fully consumed; reuse sbuf for reduction

    #pragma unroll
    for (int f = 0; f < NF; f++) sbuf[t * 65 + f] = r[f];

    __syncthreads();

    // ---- reduce 48 thread-rows per p, write coalesced output ----
    if (t < NF) {
        float s = 0.0f;
        #pragma unroll
        for (int row = 0; row < 48; row++) s += sbuf[row * 65 + t];
        out[(size_t)(2 * blockIdx.x) * NF + t] = s;
    } else if (t >= 48 && t < 48 + NF) {
        int f = t - 48;
        float s = 0.0f;
        #pragma unroll
        for (int row = 48; row < 96; row++) s += sbuf[row * 65 + f];
        out[(size_t)(2 * blockIdx.x + 1) * NF + f] = s;
    }
}

// ---------------------------------------------------------------------------
// Launch
// ---------------------------------------------------------------------------
extern "C" void kernel_launch(void* const* d_in, const int* in_sizes, int n_in,
                              void* d_out, int out_size)
{
    const float* scalar    = (const float*)d_in[0];
    const float* srecv     = (const float*)d_in[1];
    const float* expansion = (const float*)d_in[2];
    const float* mask      = (const float*)d_in[3];
    const float* edge      = (const float*)d_in[4];
    const float* W1e       = (const float*)d_in[5];
    const float* b1e       = (const float*)d_in[6];
    const float* W2e       = (const float*)d_in[7];
    const float* b2e       = (const float*)d_in[8];
    const float* W1n       = (const float*)d_in[9];
    const float* b1n       = (const float*)d_in[10];
    const float* W2n       = (const float*)d_in[11];
    const float* b2n       = (const float*)d_in[12];
    float* out = (float*)d_out;

    // Stage W1e + biases into the constant bank (D2D async: graph-capturable)
    cudaMemcpyToSymbolAsync(cW1e, W1e, NE * NF * sizeof(float), 0,
                            cudaMemcpyDeviceToDevice, 0);
    cudaMemcpyToSymbolAsync(cb1e, b1e, NF * sizeof(float), 0,
                            cudaMemcpyDeviceToDevice, 0);
    cudaMemcpyToSymbolAsync(cb2e, b2e, NF * sizeof(float), 0,
                            cudaMemcpyDeviceToDevice, 0);
    cudaMemcpyToSymbolAsync(cb2n, b2n, NF * sizeof(float), 0,
                            cudaMemcpyDeviceToDevice, 0);

    // Precompute src/tgt linear terms: one warp per row
    int rows    = NB * NP + NB * NA;               // 8384
    int threads = 256;
    int blocks  = (rows * 32 + threads - 1) / threads;
    precompute_kernel<<<blocks, threads>>>(scalar, srecv, W1n, b1n);

    // Main fused kernel: one block per 2 (b,p)'s
    main_kernel<<<NB * NP / 2, 96>>>(expansion, mask, edge, W2e, W2n, out);
}

// round 10
// speedup vs baseline: 2.0466x; 1.2026x over previous
#include <cuda_runtime.h>
#include <cstddef>

// Problem constants (fixed by the dataset)
#define NB 2
#define NP 4096
#define NA 96
#define NF 32
#define NE 20

#define L2E 1.4426950408889634f   // log2(e)
#define LN2 0.6931471805599453f   // ln(2)

// Scratch for precomputed linear terms (pre-scaled by log2e)
__device__ float g_tgt[NB * NP * NF];   // (srecv @ Wt + b1n) * log2e
__device__ float g_src[NB * NA * NF];   // (scalar @ Ws) * log2e

// Transformed-weight scratch (written by prep_kernel, D2D-copied to const)
__device__ __align__(16) float g_W1e_s[NE * NF];  // W1e * log2e
__device__ __align__(16) float g_b1e_s[NF];       // b1e * log2e
__device__ __align__(16) float g_W2e_s[NF * NF];  // ln2 * W2e
__device__ __align__(16) float g_b2e_s[NF];       // b2e - ln2*colsum(W2e)
__device__ __align__(16) float g_W2n_s[NF * NF];  // ln2 * W2n
__device__ __align__(16) float g_b2n_s[NF];       // b2n - ln2*colsum(W2n)

// Gates weights on the constant port (R5 layout: W1e + W2e const, W2n smem)
__constant__ __align__(16) float cW1e[NE * NF];
__constant__ __align__(16) float cW2e[NF * NF];
__constant__ __align__(16) float cb1e[NF];
__constant__ __align__(16) float cb2e[NF];

// minimal softplus core: y already scaled by log2e; returns log2(1 + 2^y).
// Downstream ln2 / -ln2 shift folded into W'/b'. 2 MUFU + 1 FADD.
__device__ __forceinline__ float ssp2(float y) {
    float e, t;
    asm("ex2.approx.f32 %0, %1;" : "=f"(e) : "f"(y));
    asm("lg2.approx.f32 %0, %1;" : "=f"(t) : "f"(1.0f + e));
    return t;
}

// ---- packed f32x2 helpers (Blackwell FFMA2) --------------------------------
__device__ __forceinline__ void fma2(unsigned long long& acc,
                                     unsigned long long s2,
                                     unsigned long long w2) {
    asm("fma.rn.f32x2 %0, %1, %2, %0;" : "+l"(acc) : "l"(s2), "l"(w2));
}
__device__ __forceinline__ unsigned long long pack2(float s) {
    unsigned long long r;
    asm("mov.b64 %0, {%1, %1};" : "=l"(r) : "f"(s));
    return r;
}
__device__ __forceinline__ float2 unpk2(unsigned long long v) {
    float2 r;
    asm("mov.b64 {%0, %1}, %2;" : "=f"(r.x), "=f"(r.y) : "l"(v));
    return r;
}

// ---------------------------------------------------------------------------
// Prep kernel: write base-2-transformed weights into device scratch.
// ---------------------------------------------------------------------------
__global__ void prep_kernel(const float* __restrict__ W1e,
                            const float* __restrict__ b1e,
                            const float* __restrict__ W2e,
                            const float* __restrict__ b2e,
                            const float* __restrict__ W2n,
                            const float* __restrict__ b2n)
{
    int i = blockIdx.x * blockDim.x + threadIdx.x;
    if (i < NE * NF) g_W1e_s[i] = W1e[i] * L2E;
    if (i < NF * NF) {
        g_W2e_s[i] = W2e[i] * LN2;
        g_W2n_s[i] = W2n[i] * LN2;
    }
    if (i < NF) {
        g_b1e_s[i] = b1e[i] * L2E;
        float s2e = 0.0f, s2n = 0.0f;
        #pragma unroll
        for (int k = 0; k < NF; k++) {
            s2e += W2e[k * NF + i];
            s2n += W2n[k * NF + i];
        }
        g_b2e_s[i] = b2e[i] - LN2 * s2e;
        g_b2n_s[i] = b2n[i] - LN2 * s2n;
    }
}

// ---------------------------------------------------------------------------
// Precompute kernel: one warp per output row, lane = f. Results * log2e.
// ---------------------------------------------------------------------------
__global__ void precompute_kernel(const float* __restrict__ scalar,
                                  const float* __restrict__ srecv,
                                  const float* __restrict__ W1n,
                                  const float* __restrict__ b1n)
{
    int gw   = (blockIdx.x * blockDim.x + threadIdx.x) >> 5;
    int lane = threadIdx.x & 31;

    if (gw < NB * NP) {
        float xv  = srecv[gw * NF + lane];
        float acc = b1n[lane];
        #pragma unroll
        for (int k = 0; k < NF; k++) {
            float xk = __shfl_sync(0xffffffffu, xv, k);
            acc = fmaf(xk, W1n[(NF + k) * NF + lane], acc);
        }
        g_tgt[gw * NF + lane] = acc * L2E;
    } else if (gw < NB * NP + NB * NA) {
        int r = gw - NB * NP;
        float xv  = scalar[r * NF + lane];
        float acc = 0.0f;
        #pragma unroll
        for (int k = 0; k < NF; k++) {
            float xk = __shfl_sync(0xffffffffu, xv, k);
            acc = fmaf(xk, W1n[k * NF + lane], acc);
        }
        g_src[r * NF + lane] = acc * L2E;
    }
}

// ---------------------------------------------------------------------------
// Main kernel: exact R5 structure (best: 127.5us), with the base-2 minimal
// softplus (2 MUFU + 1 FADD vs 2 MUFU + ~6 ALU; dep chain 52 -> 36 cyc).
// block = 2 (b,p)'s; thread = 2 edges (a, a+48) of one p.
// ---------------------------------------------------------------------------
__global__ __launch_bounds__(96, 4) void main_kernel(
    const float* __restrict__ expansion,   // (B,P,A,E)
    const float* __restrict__ mask,        // (B,P,A,1)
    const float* __restrict__ edge,        // (B,P,A,1)
    float* __restrict__ out)               // (B,P,1,F)
{
    __shared__ __align__(16) float sW2n[NF * NF];
    __shared__ __align__(16) float sb2n[NF];
    __shared__ __align__(16) float stgt[2][NF];
    // Reused: gate stash (64 f/thread, stride 65) then reduction buffer.
    __shared__ float sbuf[96 * 65];

    const int t   = threadIdx.x;          // 0..95
    const int pl  = t / 48;               // which p within the block
    const int ai  = t - pl * 48;          // 0..47
    const int bp  = 2 * blockIdx.x + pl;  // global b*NP+p
    const int b   = bp >> 12;             // NP == 4096
    const int a0  = ai;                   // first edge
    const int a1  = ai + 48;              // second edge

    // ---- cooperative staging ----
    for (int i = t; i < NF * NF; i += 96) sW2n[i] = g_W2n_s[i];
    if (t < NF) {
        sb2n[t] = g_b2n_s[t];
        stgt[0][t] = g_tgt[(size_t)(2 * blockIdx.x) * NF + t];
        stgt[1][t] = g_tgt[(size_t)(2 * blockIdx.x + 1) * NF + t];
    }
    __syncthreads();

    // ---- per-item edge data ----
    const size_t base0 = (size_t)bp * NA + a0;
    const size_t base1 = (size_t)bp * NA + a1;

    float x0[NE], x1[NE];
    {
        const float4* r0 = reinterpret_cast<const float4*>(expansion + base0 * NE);
        const float4* r1 = reinterpret_cast<const float4*>(expansion + base1 * NE);
        #pragma unroll
        for (int i = 0; i < NE / 4; i++) {
            float4 v0 = r0[i], v1 = r1[i];
            x0[4*i+0] = v0.x; x0[4*i+1] = v0.y; x0[4*i+2] = v0.z; x0[4*i+3] = v0.w;
            x1[4*i+0] = v1.x; x1[4*i+1] = v1.y; x1[4*i+2] = v1.z; x1[4*i+3] = v1.w;
        }
    }
    float gm0, gm1;
    {
        float m0 = mask[base0], m1 = mask[base1];
        float d0 = edge[base0], d1 = edge[base1];
        // sigmoid cutoff in base-2: 1/(1+2^{5*log2e*(d-3.5)})
        float u0, u1;
        asm("ex2.approx.f32 %0, %1;" : "=f"(u0) : "f"((d0 - 3.5f) * (5.0f * L2E)));
        asm("ex2.approx.f32 %0, %1;" : "=f"(u1) : "f"((d1 - 3.5f) * (5.0f * L2E)));
        gm0 = __fdividef(m0, 1.0f + u0);
        gm1 = __fdividef(m1, 1.0f + u1);
    }

    // ===== gates layer 1: (x @ W1e' + b1e')  [weights: constant port] =====
    unsigned long long acc0[NF / 2], acc1[NF / 2];
    {
        const unsigned long long* bb = reinterpret_cast<const unsigned long long*>(cb1e);
        #pragma unroll
        for (int j = 0; j < NF / 2; j++) { acc0[j] = bb[j]; acc1[j] = bb[j]; }
    }
    #pragma unroll
    for (int e = 0; e < NE; e++) {
        unsigned long long s0 = pack2(x0[e]);
        unsigned long long s1 = pack2(x1[e]);
        const ulonglong2* w4 = reinterpret_cast<const ulonglong2*>(&cW1e[e * NF]);
        #pragma unroll
        for (int j = 0; j < NF / 4; j++) {
            ulonglong2 w = w4[j];
            fma2(acc0[2*j+0], s0, w.x); fma2(acc1[2*j+0], s1, w.x);
            fma2(acc0[2*j+1], s0, w.y); fma2(acc1[2*j+1], s1, w.y);
        }
    }
    float e1g0[NF], e1g1[NF];
    #pragma unroll
    for (int j = 0; j < NF / 2; j++) {
        float2 v0 = unpk2(acc0[j]), v1 = unpk2(acc1[j]);
        e1g0[2*j+0] = ssp2(v0.x); e1g0[2*j+1] = ssp2(v0.y);
        e1g1[2*j+0] = ssp2(v1.x); e1g1[2*j+1] = ssp2(v1.y);
    }

    // ===== gates layer 2: @ W2e' + b2e'  [weights: constant port] =====
    {
        const unsigned long long* bb = reinterpret_cast<const unsigned long long*>(cb2e);
        #pragma unroll
        for (int j = 0; j < NF / 2; j++) { acc0[j] = bb[j]; acc1[j] = bb[j]; }
    }
    #pragma unroll
    for (int k = 0; k < NF; k++) {
        unsigned long long s0 = pack2(e1g0[k]);
        unsigned long long s1 = pack2(e1g1[k]);
        const ulonglong2* w4 = reinterpret_cast<const ulonglong2*>(&cW2e[k * NF]);
        #pragma unroll
        for (int j = 0; j < NF / 4; j++) {
            ulonglong2 w = w4[j];
            fma2(acc0[2*j+0], s0, w.x); fma2(acc1[2*j+0], s1, w.x);
            fma2(acc0[2*j+1], s0, w.y); fma2(acc1[2*j+1], s1, w.y);
        }
    }
    // stash gm * gate to smem (frees 64 registers for the nodes GEMM)
    {
        float* st = &sbuf[t * 65];
        #pragma unroll
        for (int j = 0; j < NF / 2; j++) {
            float2 v0 = unpk2(acc0[j]), v1 = unpk2(acc1[j]);
            st[2*j+0]      = gm0 * v0.x;  st[2*j+1]      = gm0 * v0.y;
            st[NF + 2*j+0] = gm1 * v1.x;  st[NF + 2*j+1] = gm1 * v1.y;
        }
    }

    // ===== nodes path: ssp2(src'[a] + tgt'[p]) @ W2n' + b2n'  [smem] ========
    float n1g0[NF], n1g1[NF];
    {
        const float4* s0 = reinterpret_cast<const float4*>(g_src + ((size_t)b * NA + a0) * NF);
        const float4* s1 = reinterpret_cast<const float4*>(g_src + ((size_t)b * NA + a1) * NF);
        #pragma unroll
        for (int q = 0; q < NF / 4; q++) {
            float4 v0 = s0[q], v1 = s1[q];
            float t0 = stgt[pl][4*q+0], t1 = stgt[pl][4*q+1];
            float t2 = stgt[pl][4*q+2], t3 = stgt[pl][4*q+3];
            n1g0[4*q+0] = ssp2(v0.x + t0); n1g0[4*q+1] = ssp2(v0.y + t1);
            n1g0[4*q+2] = ssp2(v0.z + t2); n1g0[4*q+3] = ssp2(v0.w + t3);
            n1g1[4*q+0] = ssp2(v1.x + t0); n1g1[4*q+1] = ssp2(v1.y + t1);
            n1g1[4*q+2] = ssp2(v1.z + t2); n1g1[4*q+3] = ssp2(v1.w + t3);
        }
    }
    {
        const unsigned long long* bb = reinterpret_cast<const unsigned long long*>(sb2n);
        #pragma unroll
        for (int j = 0; j < NF / 2; j++) { acc0[j] = bb[j]; acc1[j] = bb[j]; }
    }
    #pragma unroll
    for (int k = 0; k < NF; k++) {
        unsigned long long s0 = pack2(n1g0[k]);
        unsigned long long s1 = pack2(n1g1[k]);
        const ulonglong2* w4 = reinterpret_cast<const ulonglong2*>(&sW2n[k * NF]);
        #pragma unroll
        for (int j = 0; j < NF / 4; j++) {
            ulonglong2 w = w4[j];
            fma2(acc0[2*j+0], s0, w.x); fma2(acc1[2*j+0], s1, w.x);
            fma2(acc0[2*j+1], s0, w.y); fma2(acc1[2*j+1], s1, w.y);
        }
    }

    // ---- combine both items in registers: r_f = st0_f*n0_f + st1_f*n1_f ----
    float r[NF];
    {
        const float* st = &sbuf[t * 65];
        #pragma unroll
        for (int j = 0; j < NF / 2; j++) {
            float2 v0 = unpk2(acc0[j]), v1 = unpk2(acc1[j]);
            r[2*j+0] = fmaf(st[2*j+0], v0.x, st[NF + 2*j+0] * v1.x);
            r[2*j+1] = fmaf(st[2*j+1], v0.y, st[NF + 2*j+1] * v1.y);
        }
    }

    __syncthreads();   // stash fully consumed; reuse sbuf for reduction

    #pragma unroll
    for (int f = 0; f < NF; f++) sbuf[t * 65 + f] = r[f];

    __syncthreads();

    // ---- reduce 48 thread-rows per p, write coalesced output ----
    if (t < NF) {
        float s = 0.0f;
        #pragma unroll
        for (int row = 0; row < 48; row++) s += sbuf[row * 65 + t];
        out[(size_t)(2 * blockIdx.x) * NF + t] = s;
    } else if (t >= 48 && t < 48 + NF) {
        int f = t - 48;
        float s = 0.0f;
        #pragma unroll
        for (int row = 48; row < 96; row++) s += sbuf[row * 65 + f];
        out[(size_t)(2 * blockIdx.x + 1) * NF + f] = s;
    }
}

// ---------------------------------------------------------------------------
// Launch
// ---------------------------------------------------------------------------
extern "C" void kernel_launch(void* const* d_in, const int* in_sizes, int n_in,
                              void* d_out, int out_size)
{
    const float* scalar    = (const float*)d_in[0];
    const float* srecv     = (const float*)d_in[1];
    const float* expansion = (const float*)d_in[2];
    const float* mask      = (const float*)d_in[3];
    const float* edge      = (const float*)d_in[4];
    const float* W1e       = (const float*)d_in[5];
    const float* b1e       = (const float*)d_in[6];
    const float* W2e       = (const float*)d_in[7];
    const float* b2e       = (const float*)d_in[8];
    const float* W1n       = (const float*)d_in[9];
    const float* b1n       = (const float*)d_in[10];
    const float* W2n       = (const float*)d_in[11];
    const float* b2n       = (const float*)d_in[12];
    float* out = (float*)d_out;

    // 1) Transform weights into device scratch
    prep_kernel<<<1, 1024>>>(W1e, b1e, W2e, b2e, W2n, b2n);

    // 2) Copy transformed gates weights into the constant bank (D2D async)
    void *pW1e = nullptr, *pb1e = nullptr, *pW2e = nullptr, *pb2e = nullptr;
    cudaGetSymbolAddress(&pW1e, g_W1e_s);
    cudaGetSymbolAddress(&pb1e, g_b1e_s);
    cudaGetSymbolAddress(&pW2e, g_W2e_s);
    cudaGetSymbolAddress(&pb2e, g_b2e_s);
    cudaMemcpyToSymbolAsync(cW1e, pW1e, NE * NF * sizeof(float), 0,
                            cudaMemcpyDeviceToDevice, 0);
    cudaMemcpyToSymbolAsync(cb1e, pb1e, NF * sizeof(float), 0,
                            cudaMemcpyDeviceToDevice, 0);
    cudaMemcpyToSymbolAsync(cW2e, pW2e, NF * NF * sizeof(float), 0,
                            cudaMemcpyDeviceToDevice, 0);
    cudaMemcpyToSymbolAsync(cb2e, pb2e, NF * sizeof(float), 0,
                            cudaMemcpyDeviceToDevice, 0);

    // 3) Precompute src/tgt linear terms (pre-scaled): one warp per row
    int rows    = NB * NP + NB * NA;               // 8384
    int threads = 256;
    int blocks  = (rows * 32 + threads - 1) / threads;
    precompute_kernel<<<blocks, threads>>>(scalar, srecv, W1n, b1n);

    // 4) Main fused kernel: one block per 2 (b,p)'s
    main_kernel<<<NB * NP / 2, 96>>>(expansion, mask, edge, out);
}